// round 16
// baseline (speedup 1.0000x reference)
#include <cuda_runtime.h>
#include <cuda_bf16.h>
#include <cuda_fp16.h>
#include <cstdint>
#include <cstddef>

// ============================================================
// QuantizedLinear: y[M,N] = (x[M,K] . Wq[N,K]^T) * scale[N]
//                           - scale[N]*zp[N]*rowsum(x)[M] + bias[N]
//
// Two exact int8 digit GEMMs (x 16-bit split), legacy mma.sync path.
// R11/R14 (resubmit after infra failure): R7 fused tensor+dp4a kernel, plus:
//   - 3-stage cp.async pipeline with ONE __syncthreads per iter
//   - tail packing: grid 7252, first 44 CTAs process 2 tiles
// ============================================================

constexpr int DIM_M = 8192;
constexpr int DIM_K = 4096;
constexpr int DIM_N = 16384;

constexpr int BM = 128;
constexpr int BN = 128;
constexpr int BK = 128;                  // K elems per smem chunk (=128B rows)
constexpr int NITER = DIM_K / BK;        // 32
constexpr int A_BYTES = BM * BK;         // 16384 per digit
constexpr int B_BYTES = BN * BK;         // 16384
constexpr int STRIP_W = 16;              // dp4a strip width (cols)
constexpr int STRIP_BYTES = STRIP_W * BK;            // 2048
constexpr int MAIN_BYTES = 2 * A_BYTES + B_BYTES;    // 48K
constexpr int BUF_BYTES = MAIN_BYTES + STRIP_BYTES;  // 50K
constexpr int NBUF = 3;
constexpr int SMEM_BYTES = NBUF * BUF_BYTES;         // 150K

constexpr int NT_TILES = 114;            // n-tiles per band (128 cols each)
constexpr int N_STRIPS = 112;            // strips per band (16 cols each)
constexpr int C_DP = N_STRIPS * STRIP_W; // 1792 (dp4a col region)
constexpr int NT_TOTAL = (DIM_M / BM) * NT_TILES;    // 7296 tiles
constexpr int GRID = 7252;                           // 49.0 waves of 148
constexpr int DOUBLES = NT_TOTAL - GRID;             // 44 CTAs do 2 tiles
constexpr int THREADS = 256;

// weight formats
constexpr int FMT_I8 = 0, FMT_I32 = 1, FMT_F32 = 2, FMT_BF16 = 3, FMT_F16 = 4;

// ---- device scratch ----
__device__ __align__(128) int8_t g_xhi[(size_t)DIM_M * DIM_K];
__device__ __align__(128) int8_t g_xlo[(size_t)DIM_M * DIM_K];
__device__ __align__(128) int8_t g_w8 [(size_t)DIM_N * DIM_K];
__device__ float g_s16[DIM_M];
__device__ float g_rowsum[DIM_M];
__device__ int   g_wfmt;

// ============================================================
// helpers (base PTX only)
// ============================================================
__device__ __forceinline__ uint32_t smem_u32(const void* p) {
    uint32_t a;
    asm("{ .reg .u64 t; cvta.to.shared.u64 t, %1; cvt.u32.u64 %0, t; }" : "=r"(a) : "l"(p));
    return a;
}
__device__ __forceinline__ void cp_async16(uint32_t saddr, const void* gptr) {
    asm volatile("cp.async.cg.shared.global [%0], [%1], 16;" :: "r"(saddr), "l"(gptr));
}
#define CP_COMMIT() asm volatile("cp.async.commit_group;" ::: "memory")
#define CP_WAIT1()  asm volatile("cp.async.wait_group 1;" ::: "memory")
#define CP_WAIT0()  asm volatile("cp.async.wait_group 0;" ::: "memory")

__device__ __forceinline__ void ldsm_x4(uint32_t (&r)[4], uint32_t addr) {
    asm volatile("ldmatrix.sync.aligned.m8n8.x4.shared.b16 {%0,%1,%2,%3}, [%4];"
                 : "=r"(r[0]), "=r"(r[1]), "=r"(r[2]), "=r"(r[3]) : "r"(addr));
}
__device__ __forceinline__ void mma_s8(int (&c)[4], const uint32_t (&a)[4],
                                       uint32_t b0, uint32_t b1) {
    asm volatile(
        "mma.sync.aligned.m16n8k32.row.col.s32.s8.s8.s32 "
        "{%0,%1,%2,%3}, {%4,%5,%6,%7}, {%8,%9}, {%0,%1,%2,%3};"
        : "+r"(c[0]), "+r"(c[1]), "+r"(c[2]), "+r"(c[3])
        : "r"(a[0]), "r"(a[1]), "r"(a[2]), "r"(a[3]), "r"(b0), "r"(b1));
}
// swizzle on 128B rows: byte b of row r -> b ^ ((r&7)<<4)
__device__ __forceinline__ uint32_t swz(uint32_t row, uint32_t cbyte) {
    return row * 128u + (cbyte ^ ((row & 7u) << 4));
}

// ============================================================
// Weight dtype detection + canonicalization to int8
// ============================================================
__device__ __forceinline__ int f32_smallint(float v) {
    return isfinite(v) && fabsf(v) <= 128.f && v == truncf(v);
}
__global__ void detect_w_kernel(const uint32_t* __restrict__ w) {
    const int tid = threadIdx.x;
    int ok_i32 = 1, ok_f32 = 1, ok_bf16 = 1, ok_f16 = 1;
    #pragma unroll
    for (int j = 0; j < 4; ++j) {
        uint32_t u = w[tid + j * 256];
        int iv = (int)u;
        ok_i32 &= (iv >= -128 && iv <= 127);
        ok_f32 &= f32_smallint(__int_as_float(u));
        float b0 = __int_as_float((u & 0xFFFFu) << 16);
        float b1 = __int_as_float(u & 0xFFFF0000u);
        ok_bf16 &= f32_smallint(b0) & f32_smallint(b1);
        __half_raw h0r; h0r.x = (unsigned short)(u & 0xFFFFu);
        __half_raw h1r; h1r.x = (unsigned short)(u >> 16);
        ok_f16 &= f32_smallint(__half2float(__half(h0r))) &
                  f32_smallint(__half2float(__half(h1r)));
    }
    ok_i32  = __syncthreads_and(ok_i32);
    ok_f32  = __syncthreads_and(ok_f32);
    ok_bf16 = __syncthreads_and(ok_bf16);
    ok_f16  = __syncthreads_and(ok_f16);
    if (tid == 0) {
        int f = FMT_I8;
        if (ok_i32) f = FMT_I32;
        else if (ok_f32) f = FMT_F32;
        else if (ok_bf16) f = FMT_BF16;
        else if (ok_f16) f = FMT_F16;
        g_wfmt = f;
    }
}

__global__ void __launch_bounds__(256) convert_w_kernel(const void* __restrict__ wraw) {
    const int f = g_wfmt;
    const size_t n4 = (size_t)DIM_N * DIM_K / 4;
    char4* dst = (char4*)g_w8;
    const size_t stride = (size_t)gridDim.x * blockDim.x;
    size_t i = (size_t)blockIdx.x * blockDim.x + threadIdx.x;
    if (f == FMT_I8) {
        const uint32_t* src = (const uint32_t*)wraw;
        for (; i < n4; i += stride) ((uint32_t*)dst)[i] = src[i];
    } else if (f == FMT_I32) {
        const int4* src = (const int4*)wraw;
        for (; i < n4; i += stride) {
            int4 v = src[i];
            dst[i] = make_char4((char)v.x, (char)v.y, (char)v.z, (char)v.w);
        }
    } else if (f == FMT_F32) {
        const float4* src = (const float4*)wraw;
        for (; i < n4; i += stride) {
            float4 v = src[i];
            dst[i] = make_char4((char)__float2int_rn(v.x), (char)__float2int_rn(v.y),
                                (char)__float2int_rn(v.z), (char)__float2int_rn(v.w));
        }
    } else if (f == FMT_BF16) {
        const uint2* src = (const uint2*)wraw;
        for (; i < n4; i += stride) {
            uint2 v = src[i];
            float a = __int_as_float((v.x & 0xFFFFu) << 16);
            float b = __int_as_float(v.x & 0xFFFF0000u);
            float c = __int_as_float((v.y & 0xFFFFu) << 16);
            float d = __int_as_float(v.y & 0xFFFF0000u);
            dst[i] = make_char4((char)__float2int_rn(a), (char)__float2int_rn(b),
                                (char)__float2int_rn(c), (char)__float2int_rn(d));
        }
    } else {
        const uint2* src = (const uint2*)wraw;
        for (; i < n4; i += stride) {
            uint2 v = src[i];
            __half_raw r0; r0.x = (unsigned short)(v.x & 0xFFFFu);
            __half_raw r1; r1.x = (unsigned short)(v.x >> 16);
            __half_raw r2; r2.x = (unsigned short)(v.y & 0xFFFFu);
            __half_raw r3; r3.x = (unsigned short)(v.y >> 16);
            dst[i] = make_char4((char)__float2int_rn(__half2float(__half(r0))),
                                (char)__float2int_rn(__half2float(__half(r1))),
                                (char)__float2int_rn(__half2float(__half(r2))),
                                (char)__float2int_rn(__half2float(__half(r3))));
        }
    }
}

// ============================================================
// Prep: per-row 16-bit quantization of x into two int8 digits
// ============================================================
__global__ void __launch_bounds__(256) quant_x_kernel(const float* __restrict__ x) {
    __shared__ float4 srow[DIM_K / 4];
    __shared__ float red_mx[8], red_sm[8];
    const int m = blockIdx.x;
    const int tid = threadIdx.x;
    const float4* xr = (const float4*)(x + (size_t)m * DIM_K);

    float mx = 0.f, sm = 0.f;
    #pragma unroll
    for (int j = 0; j < 4; ++j) {
        float4 v = xr[tid + j * 256];
        srow[tid + j * 256] = v;
        mx = fmaxf(mx, fmaxf(fmaxf(fabsf(v.x), fabsf(v.y)), fmaxf(fabsf(v.z), fabsf(v.w))));
        sm += v.x + v.y + v.z + v.w;
    }
    #pragma unroll
    for (int o = 16; o; o >>= 1) {
        mx = fmaxf(mx, __shfl_xor_sync(0xFFFFFFFFu, mx, o));
        sm += __shfl_xor_sync(0xFFFFFFFFu, sm, o);
    }
    if ((tid & 31) == 0) { red_mx[tid >> 5] = mx; red_sm[tid >> 5] = sm; }
    __syncthreads();
    if (tid == 0) {
        float tmx = 0.f, tsm = 0.f;
        #pragma unroll
        for (int w = 0; w < 8; ++w) { tmx = fmaxf(tmx, red_mx[w]); tsm += red_sm[w]; }
        red_mx[0] = tmx; red_sm[0] = tsm;
    }
    __syncthreads();
    mx = red_mx[0];
    const float safe = fmaxf(mx, 1e-30f);
    const float inv = 32639.f / safe;          // 32639 = 256*127+127
    char4* hi = (char4*)(g_xhi + (size_t)m * DIM_K);
    char4* lo = (char4*)(g_xlo + (size_t)m * DIM_K);
    #pragma unroll
    for (int j = 0; j < 4; ++j) {
        float4 v = srow[tid + j * 256];
        int q0 = __float2int_rn(v.x * inv);
        int q1 = __float2int_rn(v.y * inv);
        int q2 = __float2int_rn(v.z * inv);
        int q3 = __float2int_rn(v.w * inv);
        int l0 = ((q0 + 128) & 255) - 128, h0 = (q0 - l0) >> 8;
        int l1 = ((q1 + 128) & 255) - 128, h1 = (q1 - l1) >> 8;
        int l2 = ((q2 + 128) & 255) - 128, h2 = (q2 - l2) >> 8;
        int l3 = ((q3 + 128) & 255) - 128, h3 = (q3 - l3) >> 8;
        hi[tid + j * 256] = make_char4((char)h0, (char)h1, (char)h2, (char)h3);
        lo[tid + j * 256] = make_char4((char)l0, (char)l1, (char)l2, (char)l3);
    }
    if (tid == 0) { g_s16[m] = safe / 32639.f; g_rowsum[m] = red_sm[0]; }
}

// ============================================================
// Main fused kernel: per tile, every warp runs tensor (128 cols)
// + interleaved dp4a strip (16 cols). 3-stage pipeline, 1 sync/iter.
// First DOUBLES CTAs process a second tile (tail packing).
// ============================================================
__global__ void __launch_bounds__(THREADS, 1) qlin_gemm(
    float* __restrict__ out,
    const float* __restrict__ scale,
    const float* __restrict__ zp,
    const float* __restrict__ bias)
{
    extern __shared__ __align__(1024) char smem[];
    const uint32_t sbase = smem_u32(smem);

    const int tid = threadIdx.x;
    const int wid = tid >> 5;
    const int lane = tid & 31;

    // tensor fragment maps (tile-independent)
    const int wm = wid & 1;
    const int wn = wid >> 1;
    const int wrow0 = wm * 64;
    const int wcol0 = wn * 32;
    const uint32_t rA = (uint32_t)(lane & 15);
    const uint32_t cA = (lane & 16) ? 16u : 0u;
    const uint32_t rB = (uint32_t)((lane & 7) + ((lane & 16) ? 8 : 0));
    const uint32_t cB = (lane & 8) ? 16u : 0u;

    // dp4a maps (tile-independent)
    const int q  = tid >> 3;             // 0..31 (row group; rows q+32i)
    const int cp = tid & 7;              // col pair within strip
    const int ldrow = tid >> 3;
    const int ldseg = tid & 7;

    const int nTiles = ((int)blockIdx.x < DOUBLES) ? 2 : 1;

    for (int tt = 0; tt < nTiles; ++tt) {
        const int tile = (tt == 0) ? (int)blockIdx.x : (GRID + (int)blockIdx.x);
        const int band = tile / NT_TILES;
        const int j    = tile % NT_TILES;
        const int m0 = band * BM;
        const int n0 = C_DP + j * BN;
        const bool has_strip = (j < N_STRIPS);
        const int strip0 = j * STRIP_W;

        const int8_t* aHiBase = g_xhi + (size_t)m0 * DIM_K;
        const int8_t* aLoBase = g_xlo + (size_t)m0 * DIM_K;
        const int8_t* bBase   = g_w8  + (size_t)n0 * DIM_K;

        auto issue_load = [&](int it, int buf) {
            const uint32_t bb = sbase + (uint32_t)buf * BUF_BYTES;
            const int k0 = it * BK;
            #pragma unroll
            for (int jj = 0; jj < 4; ++jj) {
                const int row = ldrow + jj * 32;
                const uint32_t so = swz((uint32_t)row, (uint32_t)(ldseg * 16));
                cp_async16(bb + so,               aHiBase + (size_t)row * DIM_K + k0 + ldseg * 16);
                cp_async16(bb + A_BYTES + so,     aLoBase + (size_t)row * DIM_K + k0 + ldseg * 16);
                cp_async16(bb + 2 * A_BYTES + so, bBase   + (size_t)row * DIM_K + k0 + ldseg * 16);
            }
            if (has_strip && tid < 128) {
                const int row = tid >> 3;
                const int seg = tid & 7;
                cp_async16(bb + MAIN_BYTES + swz((uint32_t)row, (uint32_t)(seg * 16)),
                           g_w8 + (size_t)(strip0 + row) * DIM_K + k0 + seg * 16);
            }
            CP_COMMIT();
        };

        int ch[4][4][4], cl[4][4][4];
        #pragma unroll
        for (int i = 0; i < 4; ++i)
            #pragma unroll
            for (int jj = 0; jj < 4; ++jj)
                #pragma unroll
                for (int k = 0; k < 4; ++k) { ch[i][jj][k] = 0; cl[i][jj][k] = 0; }

        int dH[4][2], dL[4][2];
        #pragma unroll
        for (int i = 0; i < 4; ++i) { dH[i][0] = dH[i][1] = 0; dL[i][0] = dL[i][1] = 0; }

        issue_load(0, 0);

        for (int it = 0; it < NITER; ++it) {
            if (it + 1 < NITER) { issue_load(it + 1, (it + 1) % NBUF); CP_WAIT1(); }
            else                { CP_WAIT0(); }
            __syncthreads();    // single barrier per iter (3-buffer disjointness)

            const uint32_t bb = sbase + (uint32_t)(it % NBUF) * BUF_BYTES;

            // -------- tensor path --------
            uint32_t aHi0[4], aLo0[4];
            #pragma unroll
            for (int mi = 0; mi < 4; ++mi) {
                const uint32_t row = (uint32_t)(wrow0 + mi * 16) + rA;
                const uint32_t off = swz(row, cA);
                aHi0[mi] = bb + off;
                aLo0[mi] = bb + A_BYTES + off;
            }
            uint32_t b0g[2];
            #pragma unroll
            for (int g = 0; g < 2; ++g) {
                const uint32_t row = (uint32_t)(wcol0 + g * 16) + rB;
                b0g[g] = bb + 2 * A_BYTES + swz(row, cB);
            }
            #pragma unroll
            for (int ks = 0; ks < 4; ++ks) {
                const uint32_t kx = (uint32_t)(ks << 5);
                uint32_t ahi[4][4], alo[4][4], bf[2][4];
                #pragma unroll
                for (int mi = 0; mi < 4; ++mi) {
                    ldsm_x4(ahi[mi], aHi0[mi] ^ kx);
                    ldsm_x4(alo[mi], aLo0[mi] ^ kx);
                }
                #pragma unroll
                for (int g = 0; g < 2; ++g) ldsm_x4(bf[g], b0g[g] ^ kx);
                #pragma unroll
                for (int mi = 0; mi < 4; ++mi) {
                    #pragma unroll
                    for (int ni = 0; ni < 4; ++ni) {
                        const int g = ni >> 1;
                        const int s = (ni & 1) * 2;
                        mma_s8(ch[mi][ni], ahi[mi], bf[g][s], bf[g][s + 1]);
                        mma_s8(cl[mi][ni], alo[mi], bf[g][s], bf[g][s + 1]);
                    }
                }
                // -------- interleaved dp4a strip slice --------
                if (has_strip) {
                    #pragma unroll
                    for (int h = 0; h < 2; ++h) {
                        const uint32_t seg = (uint32_t)((ks * 2 + h) * 16);
                        int4 aH4[4], aL4[4];
                        #pragma unroll
                        for (int i = 0; i < 4; ++i) {
                            const uint32_t off = (bb - sbase) + swz((uint32_t)(q + 32 * i), seg);
                            aH4[i] = *(const int4*)(smem + off);
                            aL4[i] = *(const int4*)(smem + off + A_BYTES);
                        }
                        const uint32_t sb = (bb - sbase) + MAIN_BYTES;
                        const int4 w0 = *(const int4*)(smem + sb + swz((uint32_t)(cp * 2), seg));
                        const int4 w1 = *(const int4*)(smem + sb + swz((uint32_t)(cp * 2 + 1), seg));
                        #pragma unroll
                        for (int i = 0; i < 4; ++i) {
                            dH[i][0] = __dp4a(aH4[i].x, w0.x, dH[i][0]);
                            dH[i][0] = __dp4a(aH4[i].y, w0.y, dH[i][0]);
                            dH[i][0] = __dp4a(aH4[i].z, w0.z, dH[i][0]);
                            dH[i][0] = __dp4a(aH4[i].w, w0.w, dH[i][0]);
                            dH[i][1] = __dp4a(aH4[i].x, w1.x, dH[i][1]);
                            dH[i][1] = __dp4a(aH4[i].y, w1.y, dH[i][1]);
                            dH[i][1] = __dp4a(aH4[i].z, w1.z, dH[i][1]);
                            dH[i][1] = __dp4a(aH4[i].w, w1.w, dH[i][1]);
                            dL[i][0] = __dp4a(aL4[i].x, w0.x, dL[i][0]);
                            dL[i][0] = __dp4a(aL4[i].y, w0.y, dL[i][0]);
                            dL[i][0] = __dp4a(aL4[i].z, w0.z, dL[i][0]);
                            dL[i][0] = __dp4a(aL4[i].w, w0.w, dL[i][0]);
                            dL[i][1] = __dp4a(aL4[i].x, w1.x, dL[i][1]);
                            dL[i][1] = __dp4a(aL4[i].y, w1.y, dL[i][1]);
                            dL[i][1] = __dp4a(aL4[i].z, w1.z, dL[i][1]);
                            dL[i][1] = __dp4a(aL4[i].w, w1.w, dL[i][1]);
                        }
                    }
                }
            }
        }

        // ---- tensor epilogue ----
        const int col_in = (lane & 3) * 2;
        const int row_in = lane >> 2;
        #pragma unroll
        for (int mi = 0; mi < 4; ++mi) {
            const int r0 = m0 + wrow0 + mi * 16 + row_in;
            const int r1 = r0 + 8;
            const float s0 = g_s16[r0], rs0 = g_rowsum[r0];
            const float s1 = g_s16[r1], rs1 = g_rowsum[r1];
            #pragma unroll
            for (int ni = 0; ni < 4; ++ni) {
                const int c = n0 + wcol0 + ni * 8 + col_in;
                const float scA = __ldg(scale + c),  scB = __ldg(scale + c + 1);
                const float zA  = __ldg(zp + c),     zB  = __ldg(zp + c + 1);
                const float bA  = __ldg(bias + c),   bB_ = __ldg(bias + c + 1);
                const int* H = ch[mi][ni];
                const int* L = cl[mi][ni];
                float y00 = fmaf(256.f, (float)H[0], (float)L[0]) * s0;
                float y01 = fmaf(256.f, (float)H[1], (float)L[1]) * s0;
                float y10 = fmaf(256.f, (float)H[2], (float)L[2]) * s1;
                float y11 = fmaf(256.f, (float)H[3], (float)L[3]) * s1;
                float2 v0, v1;
                v0.x = fmaf(scA, y00, fmaf(-scA * zA, rs0, bA));
                v0.y = fmaf(scB, y01, fmaf(-scB * zB, rs0, bB_));
                v1.x = fmaf(scA, y10, fmaf(-scA * zA, rs1, bA));
                v1.y = fmaf(scB, y11, fmaf(-scB * zB, rs1, bB_));
                *(float2*)(out + (size_t)r0 * DIM_N + c) = v0;
                *(float2*)(out + (size_t)r1 * DIM_N + c) = v1;
            }
        }

        // ---- dp4a strip epilogue ----
        if (has_strip) {
            const int c0 = strip0 + cp * 2;
            const float scA = __ldg(scale + c0),  scB = __ldg(scale + c0 + 1);
            const float zA  = __ldg(zp + c0),     zB  = __ldg(zp + c0 + 1);
            const float bA  = __ldg(bias + c0),   bB_ = __ldg(bias + c0 + 1);
            #pragma unroll
            for (int i = 0; i < 4; ++i) {
                const int r = m0 + q + 32 * i;
                const float s = g_s16[r], rs = g_rowsum[r];
                float y0 = fmaf(256.f, (float)dH[i][0], (float)dL[i][0]) * s;
                float y1 = fmaf(256.f, (float)dH[i][1], (float)dL[i][1]) * s;
                float2 v;
                v.x = fmaf(scA, y0, fmaf(-scA * zA, rs, bA));
                v.y = fmaf(scB, y1, fmaf(-scB * zB, rs, bB_));
                *(float2*)(out + (size_t)r * DIM_N + c0) = v;
            }
        }

        if (tt + 1 < nTiles) __syncthreads();   // clean smem handoff between tiles
    }
}

// ============================================================
// Host launch
// ============================================================
extern "C" void kernel_launch(void* const* d_in, const int* in_sizes, int n_in,
                              void* d_out, int out_size) {
    const float* x    = (const float*)d_in[0];
    const void*  wraw = d_in[1];
    const float* wsc  = (const float*)d_in[2];
    const float* wzp  = (const float*)d_in[3];
    const float* bias = (const float*)d_in[4];
    float* out = (float*)d_out;

    cudaFuncSetAttribute(qlin_gemm, cudaFuncAttributeMaxDynamicSharedMemorySize, SMEM_BYTES);

    detect_w_kernel<<<1, 256>>>((const uint32_t*)wraw);
    convert_w_kernel<<<2048, 256>>>(wraw);
    quant_x_kernel<<<DIM_M, 256>>>(x);
    qlin_gemm<<<GRID, THREADS, SMEM_BYTES>>>(out, wsc, wzp, bias);
}

// round 17
// speedup vs baseline: 1.6595x; 1.6595x over previous
#include <cuda_runtime.h>
#include <cuda_bf16.h>
#include <cuda_fp16.h>
#include <cstdint>
#include <cstddef>

// ============================================================
// QuantizedLinear: y[M,N] = (x[M,K] . Wq[N,K]^T) * scale[N]
//                           - scale[N]*zp[N]*rowsum(x)[M] + bias[N]
//
// Two exact int8 digit GEMMs (x 16-bit split), legacy mma.sync path.
// R17: exact R7 pipeline (2-stage, 2 barriers/iter — the 14.10ms
// known-good) + tail packing ONLY (grid 7252, first 44 CTAs do 2
// tiles => 49.0 waves vs 49.3). Controlled A/B vs suspected
// clock-throttled node in R16.
// ============================================================

constexpr int DIM_M = 8192;
constexpr int DIM_K = 4096;
constexpr int DIM_N = 16384;

constexpr int BM = 128;
constexpr int BN = 128;
constexpr int BK = 128;                  // K elems per smem chunk (=128B rows)
constexpr int NITER = DIM_K / BK;        // 32
constexpr int A_BYTES = BM * BK;         // 16384 per digit
constexpr int B_BYTES = BN * BK;         // 16384
constexpr int STRIP_W = 16;              // dp4a strip width (cols)
constexpr int STRIP_BYTES = STRIP_W * BK;            // 2048
constexpr int MAIN_BYTES = 2 * A_BYTES + B_BYTES;    // 48K
constexpr int BUF_BYTES = MAIN_BYTES + STRIP_BYTES;  // 50K
constexpr int SMEM_BYTES = 2 * BUF_BYTES;            // 100K  (R7 structure)

constexpr int NT_TILES = 114;            // n-tiles per band (128 cols each)
constexpr int N_STRIPS = 112;            // strips per band (16 cols each)
constexpr int C_DP = N_STRIPS * STRIP_W; // 1792 (dp4a col region)
constexpr int NT_TOTAL = (DIM_M / BM) * NT_TILES;    // 7296 tiles
constexpr int GRID = 7252;                           // 49.0 waves of 148
constexpr int DOUBLES = NT_TOTAL - GRID;             // 44 CTAs do 2 tiles
constexpr int THREADS = 256;

// weight formats
constexpr int FMT_I8 = 0, FMT_I32 = 1, FMT_F32 = 2, FMT_BF16 = 3, FMT_F16 = 4;

// ---- device scratch ----
__device__ __align__(128) int8_t g_xhi[(size_t)DIM_M * DIM_K];
__device__ __align__(128) int8_t g_xlo[(size_t)DIM_M * DIM_K];
__device__ __align__(128) int8_t g_w8 [(size_t)DIM_N * DIM_K];
__device__ float g_s16[DIM_M];
__device__ float g_rowsum[DIM_M];
__device__ int   g_wfmt;

// ============================================================
// helpers (base PTX only)
// ============================================================
__device__ __forceinline__ uint32_t smem_u32(const void* p) {
    uint32_t a;
    asm("{ .reg .u64 t; cvta.to.shared.u64 t, %1; cvt.u32.u64 %0, t; }" : "=r"(a) : "l"(p));
    return a;
}
__device__ __forceinline__ void cp_async16(uint32_t saddr, const void* gptr) {
    asm volatile("cp.async.cg.shared.global [%0], [%1], 16;" :: "r"(saddr), "l"(gptr));
}
#define CP_COMMIT() asm volatile("cp.async.commit_group;" ::: "memory")
#define CP_WAIT1()  asm volatile("cp.async.wait_group 1;" ::: "memory")
#define CP_WAIT0()  asm volatile("cp.async.wait_group 0;" ::: "memory")

__device__ __forceinline__ void ldsm_x4(uint32_t (&r)[4], uint32_t addr) {
    asm volatile("ldmatrix.sync.aligned.m8n8.x4.shared.b16 {%0,%1,%2,%3}, [%4];"
                 : "=r"(r[0]), "=r"(r[1]), "=r"(r[2]), "=r"(r[3]) : "r"(addr));
}
__device__ __forceinline__ void mma_s8(int (&c)[4], const uint32_t (&a)[4],
                                       uint32_t b0, uint32_t b1) {
    asm volatile(
        "mma.sync.aligned.m16n8k32.row.col.s32.s8.s8.s32 "
        "{%0,%1,%2,%3}, {%4,%5,%6,%7}, {%8,%9}, {%0,%1,%2,%3};"
        : "+r"(c[0]), "+r"(c[1]), "+r"(c[2]), "+r"(c[3])
        : "r"(a[0]), "r"(a[1]), "r"(a[2]), "r"(a[3]), "r"(b0), "r"(b1));
}
// swizzle on 128B rows: byte b of row r -> b ^ ((r&7)<<4)
__device__ __forceinline__ uint32_t swz(uint32_t row, uint32_t cbyte) {
    return row * 128u + (cbyte ^ ((row & 7u) << 4));
}

// ============================================================
// Weight dtype detection + canonicalization to int8
// ============================================================
__device__ __forceinline__ int f32_smallint(float v) {
    return isfinite(v) && fabsf(v) <= 128.f && v == truncf(v);
}
__global__ void detect_w_kernel(const uint32_t* __restrict__ w) {
    const int tid = threadIdx.x;
    int ok_i32 = 1, ok_f32 = 1, ok_bf16 = 1, ok_f16 = 1;
    #pragma unroll
    for (int j = 0; j < 4; ++j) {
        uint32_t u = w[tid + j * 256];
        int iv = (int)u;
        ok_i32 &= (iv >= -128 && iv <= 127);
        ok_f32 &= f32_smallint(__int_as_float(u));
        float b0 = __int_as_float((u & 0xFFFFu) << 16);
        float b1 = __int_as_float(u & 0xFFFF0000u);
        ok_bf16 &= f32_smallint(b0) & f32_smallint(b1);
        __half_raw h0r; h0r.x = (unsigned short)(u & 0xFFFFu);
        __half_raw h1r; h1r.x = (unsigned short)(u >> 16);
        ok_f16 &= f32_smallint(__half2float(__half(h0r))) &
                  f32_smallint(__half2float(__half(h1r)));
    }
    ok_i32  = __syncthreads_and(ok_i32);
    ok_f32  = __syncthreads_and(ok_f32);
    ok_bf16 = __syncthreads_and(ok_bf16);
    ok_f16  = __syncthreads_and(ok_f16);
    if (tid == 0) {
        int f = FMT_I8;
        if (ok_i32) f = FMT_I32;
        else if (ok_f32) f = FMT_F32;
        else if (ok_bf16) f = FMT_BF16;
        else if (ok_f16) f = FMT_F16;
        g_wfmt = f;
    }
}

__global__ void __launch_bounds__(256) convert_w_kernel(const void* __restrict__ wraw) {
    const int f = g_wfmt;
    const size_t n4 = (size_t)DIM_N * DIM_K / 4;
    char4* dst = (char4*)g_w8;
    const size_t stride = (size_t)gridDim.x * blockDim.x;
    size_t i = (size_t)blockIdx.x * blockDim.x + threadIdx.x;
    if (f == FMT_I8) {
        const uint32_t* src = (const uint32_t*)wraw;
        for (; i < n4; i += stride) ((uint32_t*)dst)[i] = src[i];
    } else if (f == FMT_I32) {
        const int4* src = (const int4*)wraw;
        for (; i < n4; i += stride) {
            int4 v = src[i];
            dst[i] = make_char4((char)v.x, (char)v.y, (char)v.z, (char)v.w);
        }
    } else if (f == FMT_F32) {
        const float4* src = (const float4*)wraw;
        for (; i < n4; i += stride) {
            float4 v = src[i];
            dst[i] = make_char4((char)__float2int_rn(v.x), (char)__float2int_rn(v.y),
                                (char)__float2int_rn(v.z), (char)__float2int_rn(v.w));
        }
    } else if (f == FMT_BF16) {
        const uint2* src = (const uint2*)wraw;
        for (; i < n4; i += stride) {
            uint2 v = src[i];
            float a = __int_as_float((v.x & 0xFFFFu) << 16);
            float b = __int_as_float(v.x & 0xFFFF0000u);
            float c = __int_as_float((v.y & 0xFFFFu) << 16);
            float d = __int_as_float(v.y & 0xFFFF0000u);
            dst[i] = make_char4((char)__float2int_rn(a), (char)__float2int_rn(b),
                                (char)__float2int_rn(c), (char)__float2int_rn(d));
        }
    } else {
        const uint2* src = (const uint2*)wraw;
        for (; i < n4; i += stride) {
            uint2 v = src[i];
            __half_raw r0; r0.x = (unsigned short)(v.x & 0xFFFFu);
            __half_raw r1; r1.x = (unsigned short)(v.x >> 16);
            __half_raw r2; r2.x = (unsigned short)(v.y & 0xFFFFu);
            __half_raw r3; r3.x = (unsigned short)(v.y >> 16);
            dst[i] = make_char4((char)__float2int_rn(__half2float(__half(r0))),
                                (char)__float2int_rn(__half2float(__half(r1))),
                                (char)__float2int_rn(__half2float(__half(r2))),
                                (char)__float2int_rn(__half2float(__half(r3))));
        }
    }
}

// ============================================================
// Prep: per-row 16-bit quantization of x into two int8 digits
// ============================================================
__global__ void __launch_bounds__(256) quant_x_kernel(const float* __restrict__ x) {
    __shared__ float4 srow[DIM_K / 4];
    __shared__ float red_mx[8], red_sm[8];
    const int m = blockIdx.x;
    const int tid = threadIdx.x;
    const float4* xr = (const float4*)(x + (size_t)m * DIM_K);

    float mx = 0.f, sm = 0.f;
    #pragma unroll
    for (int j = 0; j < 4; ++j) {
        float4 v = xr[tid + j * 256];
        srow[tid + j * 256] = v;
        mx = fmaxf(mx, fmaxf(fmaxf(fabsf(v.x), fabsf(v.y)), fmaxf(fabsf(v.z), fabsf(v.w))));
        sm += v.x + v.y + v.z + v.w;
    }
    #pragma unroll
    for (int o = 16; o; o >>= 1) {
        mx = fmaxf(mx, __shfl_xor_sync(0xFFFFFFFFu, mx, o));
        sm += __shfl_xor_sync(0xFFFFFFFFu, sm, o);
    }
    if ((tid & 31) == 0) { red_mx[tid >> 5] = mx; red_sm[tid >> 5] = sm; }
    __syncthreads();
    if (tid == 0) {
        float tmx = 0.f, tsm = 0.f;
        #pragma unroll
        for (int w = 0; w < 8; ++w) { tmx = fmaxf(tmx, red_mx[w]); tsm += red_sm[w]; }
        red_mx[0] = tmx; red_sm[0] = tsm;
    }
    __syncthreads();
    mx = red_mx[0];
    const float safe = fmaxf(mx, 1e-30f);
    const float inv = 32639.f / safe;          // 32639 = 256*127+127
    char4* hi = (char4*)(g_xhi + (size_t)m * DIM_K);
    char4* lo = (char4*)(g_xlo + (size_t)m * DIM_K);
    #pragma unroll
    for (int j = 0; j < 4; ++j) {
        float4 v = srow[tid + j * 256];
        int q0 = __float2int_rn(v.x * inv);
        int q1 = __float2int_rn(v.y * inv);
        int q2 = __float2int_rn(v.z * inv);
        int q3 = __float2int_rn(v.w * inv);
        int l0 = ((q0 + 128) & 255) - 128, h0 = (q0 - l0) >> 8;
        int l1 = ((q1 + 128) & 255) - 128, h1 = (q1 - l1) >> 8;
        int l2 = ((q2 + 128) & 255) - 128, h2 = (q2 - l2) >> 8;
        int l3 = ((q3 + 128) & 255) - 128, h3 = (q3 - l3) >> 8;
        hi[tid + j * 256] = make_char4((char)h0, (char)h1, (char)h2, (char)h3);
        lo[tid + j * 256] = make_char4((char)l0, (char)l1, (char)l2, (char)l3);
    }
    if (tid == 0) { g_s16[m] = safe / 32639.f; g_rowsum[m] = red_sm[0]; }
}

// ============================================================
// Main fused kernel (R7 structure): per tile, every warp runs
// tensor (128 cols) + interleaved dp4a strip (16 cols).
// 2-stage pipeline, 2 barriers/iter. Tail packing on top.
// ============================================================
__global__ void __launch_bounds__(THREADS, 1) qlin_gemm(
    float* __restrict__ out,
    const float* __restrict__ scale,
    const float* __restrict__ zp,
    const float* __restrict__ bias)
{
    extern __shared__ __align__(1024) char smem[];
    const uint32_t sbase = smem_u32(smem);

    const int tid = threadIdx.x;
    const int wid = tid >> 5;
    const int lane = tid & 31;

    // tensor fragment maps (tile-independent)
    const int wm = wid & 1;
    const int wn = wid >> 1;
    const int wrow0 = wm * 64;
    const int wcol0 = wn * 32;
    const uint32_t rA = (uint32_t)(lane & 15);
    const uint32_t cA = (lane & 16) ? 16u : 0u;
    const uint32_t rB = (uint32_t)((lane & 7) + ((lane & 16) ? 8 : 0));
    const uint32_t cB = (lane & 8) ? 16u : 0u;

    // dp4a maps (tile-independent)
    const int q  = tid >> 3;             // 0..31 (row group; rows q+32i)
    const int cp = tid & 7;              // col pair within strip
    const int ldrow = tid >> 3;
    const int ldseg = tid & 7;

    const int nTiles = ((int)blockIdx.x < DOUBLES) ? 2 : 1;

    for (int tt = 0; tt < nTiles; ++tt) {
        const int tile = (tt == 0) ? (int)blockIdx.x : (GRID + (int)blockIdx.x);
        const int band = tile / NT_TILES;
        const int j    = tile % NT_TILES;
        const int m0 = band * BM;
        const int n0 = C_DP + j * BN;
        const bool has_strip = (j < N_STRIPS);
        const int strip0 = j * STRIP_W;

        const int8_t* aHiBase = g_xhi + (size_t)m0 * DIM_K;
        const int8_t* aLoBase = g_xlo + (size_t)m0 * DIM_K;
        const int8_t* bBase   = g_w8  + (size_t)n0 * DIM_K;

        auto issue_load = [&](int it, int buf) {
            const uint32_t bb = sbase + (uint32_t)buf * BUF_BYTES;
            const int k0 = it * BK;
            #pragma unroll
            for (int jj = 0; jj < 4; ++jj) {
                const int row = ldrow + jj * 32;
                const uint32_t so = swz((uint32_t)row, (uint32_t)(ldseg * 16));
                cp_async16(bb + so,               aHiBase + (size_t)row * DIM_K + k0 + ldseg * 16);
                cp_async16(bb + A_BYTES + so,     aLoBase + (size_t)row * DIM_K + k0 + ldseg * 16);
                cp_async16(bb + 2 * A_BYTES + so, bBase   + (size_t)row * DIM_K + k0 + ldseg * 16);
            }
            if (has_strip && tid < 128) {
                const int row = tid >> 3;
                const int seg = tid & 7;
                cp_async16(bb + MAIN_BYTES + swz((uint32_t)row, (uint32_t)(seg * 16)),
                           g_w8 + (size_t)(strip0 + row) * DIM_K + k0 + seg * 16);
            }
            CP_COMMIT();
        };

        int ch[4][4][4], cl[4][4][4];
        #pragma unroll
        for (int i = 0; i < 4; ++i)
            #pragma unroll
            for (int jj = 0; jj < 4; ++jj)
                #pragma unroll
                for (int k = 0; k < 4; ++k) { ch[i][jj][k] = 0; cl[i][jj][k] = 0; }

        int dH[4][2], dL[4][2];
        #pragma unroll
        for (int i = 0; i < 4; ++i) { dH[i][0] = dH[i][1] = 0; dL[i][0] = dL[i][1] = 0; }

        issue_load(0, 0);

        for (int it = 0; it < NITER; ++it) {
            if (it + 1 < NITER) { issue_load(it + 1, (it + 1) & 1); CP_WAIT1(); }
            else                { CP_WAIT0(); }
            __syncthreads();

            const uint32_t bb = sbase + (uint32_t)(it & 1) * BUF_BYTES;

            // -------- tensor path --------
            uint32_t aHi0[4], aLo0[4];
            #pragma unroll
            for (int mi = 0; mi < 4; ++mi) {
                const uint32_t row = (uint32_t)(wrow0 + mi * 16) + rA;
                const uint32_t off = swz(row, cA);
                aHi0[mi] = bb + off;
                aLo0[mi] = bb + A_BYTES + off;
            }
            uint32_t b0g[2];
            #pragma unroll
            for (int g = 0; g < 2; ++g) {
                const uint32_t row = (uint32_t)(wcol0 + g * 16) + rB;
                b0g[g] = bb + 2 * A_BYTES + swz(row, cB);
            }
            #pragma unroll
            for (int ks = 0; ks < 4; ++ks) {
                const uint32_t kx = (uint32_t)(ks << 5);
                uint32_t ahi[4][4], alo[4][4], bf[2][4];
                #pragma unroll
                for (int mi = 0; mi < 4; ++mi) {
                    ldsm_x4(ahi[mi], aHi0[mi] ^ kx);
                    ldsm_x4(alo[mi], aLo0[mi] ^ kx);
                }
                #pragma unroll
                for (int g = 0; g < 2; ++g) ldsm_x4(bf[g], b0g[g] ^ kx);
                #pragma unroll
                for (int mi = 0; mi < 4; ++mi) {
                    #pragma unroll
                    for (int ni = 0; ni < 4; ++ni) {
                        const int g = ni >> 1;
                        const int s = (ni & 1) * 2;
                        mma_s8(ch[mi][ni], ahi[mi], bf[g][s], bf[g][s + 1]);
                        mma_s8(cl[mi][ni], alo[mi], bf[g][s], bf[g][s + 1]);
                    }
                }
                // -------- interleaved dp4a strip slice --------
                if (has_strip) {
                    #pragma unroll
                    for (int h = 0; h < 2; ++h) {
                        const uint32_t seg = (uint32_t)((ks * 2 + h) * 16);
                        int4 aH4[4], aL4[4];
                        #pragma unroll
                        for (int i = 0; i < 4; ++i) {
                            const uint32_t off = (bb - sbase) + swz((uint32_t)(q + 32 * i), seg);
                            aH4[i] = *(const int4*)(smem + off);
                            aL4[i] = *(const int4*)(smem + off + A_BYTES);
                        }
                        const uint32_t sb = (bb - sbase) + MAIN_BYTES;
                        const int4 w0 = *(const int4*)(smem + sb + swz((uint32_t)(cp * 2), seg));
                        const int4 w1 = *(const int4*)(smem + sb + swz((uint32_t)(cp * 2 + 1), seg));
                        #pragma unroll
                        for (int i = 0; i < 4; ++i) {
                            dH[i][0] = __dp4a(aH4[i].x, w0.x, dH[i][0]);
                            dH[i][0] = __dp4a(aH4[i].y, w0.y, dH[i][0]);
                            dH[i][0] = __dp4a(aH4[i].z, w0.z, dH[i][0]);
                            dH[i][0] = __dp4a(aH4[i].w, w0.w, dH[i][0]);
                            dH[i][1] = __dp4a(aH4[i].x, w1.x, dH[i][1]);
                            dH[i][1] = __dp4a(aH4[i].y, w1.y, dH[i][1]);
                            dH[i][1] = __dp4a(aH4[i].z, w1.z, dH[i][1]);
                            dH[i][1] = __dp4a(aH4[i].w, w1.w, dH[i][1]);
                            dL[i][0] = __dp4a(aL4[i].x, w0.x, dL[i][0]);
                            dL[i][0] = __dp4a(aL4[i].y, w0.y, dL[i][0]);
                            dL[i][0] = __dp4a(aL4[i].z, w0.z, dL[i][0]);
                            dL[i][0] = __dp4a(aL4[i].w, w0.w, dL[i][0]);
                            dL[i][1] = __dp4a(aL4[i].x, w1.x, dL[i][1]);
                            dL[i][1] = __dp4a(aL4[i].y, w1.y, dL[i][1]);
                            dL[i][1] = __dp4a(aL4[i].z, w1.z, dL[i][1]);
                            dL[i][1] = __dp4a(aL4[i].w, w1.w, dL[i][1]);
                        }
                    }
                }
            }
            __syncthreads();
        }

        // ---- tensor epilogue ----
        const int col_in = (lane & 3) * 2;
        const int row_in = lane >> 2;
        #pragma unroll
        for (int mi = 0; mi < 4; ++mi) {
            const int r0 = m0 + wrow0 + mi * 16 + row_in;
            const int r1 = r0 + 8;
            const float s0 = g_s16[r0], rs0 = g_rowsum[r0];
            const float s1 = g_s16[r1], rs1 = g_rowsum[r1];
            #pragma unroll
            for (int ni = 0; ni < 4; ++ni) {
                const int c = n0 + wcol0 + ni * 8 + col_in;
                const float scA = __ldg(scale + c),  scB = __ldg(scale + c + 1);
                const float zA  = __ldg(zp + c),     zB  = __ldg(zp + c + 1);
                const float bA  = __ldg(bias + c),   bB_ = __ldg(bias + c + 1);
                const int* H = ch[mi][ni];
                const int* L = cl[mi][ni];
                float y00 = fmaf(256.f, (float)H[0], (float)L[0]) * s0;
                float y01 = fmaf(256.f, (float)H[1], (float)L[1]) * s0;
                float y10 = fmaf(256.f, (float)H[2], (float)L[2]) * s1;
                float y11 = fmaf(256.f, (float)H[3], (float)L[3]) * s1;
                float2 v0, v1;
                v0.x = fmaf(scA, y00, fmaf(-scA * zA, rs0, bA));
                v0.y = fmaf(scB, y01, fmaf(-scB * zB, rs0, bB_));
                v1.x = fmaf(scA, y10, fmaf(-scA * zA, rs1, bA));
                v1.y = fmaf(scB, y11, fmaf(-scB * zB, rs1, bB_));
                *(float2*)(out + (size_t)r0 * DIM_N + c) = v0;
                *(float2*)(out + (size_t)r1 * DIM_N + c) = v1;
            }
        }

        // ---- dp4a strip epilogue ----
        if (has_strip) {
            const int c0 = strip0 + cp * 2;
            const float scA = __ldg(scale + c0),  scB = __ldg(scale + c0 + 1);
            const float zA  = __ldg(zp + c0),     zB  = __ldg(zp + c0 + 1);
            const float bA  = __ldg(bias + c0),   bB_ = __ldg(bias + c0 + 1);
            #pragma unroll
            for (int i = 0; i < 4; ++i) {
                const int r = m0 + q + 32 * i;
                const float s = g_s16[r], rs = g_rowsum[r];
                float y0 = fmaf(256.f, (float)dH[i][0], (float)dL[i][0]) * s;
                float y1 = fmaf(256.f, (float)dH[i][1], (float)dL[i][1]) * s;
                float2 v;
                v.x = fmaf(scA, y0, fmaf(-scA * zA, rs, bA));
                v.y = fmaf(scB, y1, fmaf(-scB * zB, rs, bB_));
                *(float2*)(out + (size_t)r * DIM_N + c0) = v;
            }
        }

        if (tt + 1 < nTiles) __syncthreads();   // clean smem handoff between tiles
    }
}

// ============================================================
// Host launch
// ============================================================
extern "C" void kernel_launch(void* const* d_in, const int* in_sizes, int n_in,
                              void* d_out, int out_size) {
    const float* x    = (const float*)d_in[0];
    const void*  wraw = d_in[1];
    const float* wsc  = (const float*)d_in[2];
    const float* wzp  = (const float*)d_in[3];
    const float* bias = (const float*)d_in[4];
    float* out = (float*)d_out;

    cudaFuncSetAttribute(qlin_gemm, cudaFuncAttributeMaxDynamicSharedMemorySize, SMEM_BYTES);

    detect_w_kernel<<<1, 256>>>((const uint32_t*)wraw);
    convert_w_kernel<<<2048, 256>>>(wraw);
    quant_x_kernel<<<DIM_M, 256>>>(x);
    qlin_gemm<<<GRID, THREADS, SMEM_BYTES>>>(out, wsc, wzp, bias);
}